// round 1
// baseline (speedup 1.0000x reference)
#include <cuda_runtime.h>
#include <float.h>

#define BATCH 64
#define TOK   2048
#define DIM   768
#define POOL  1024
#define TOPK  8
#define SPLITS 32
#define TOKS  (TOK / SPLITS)   // 64 tokens per split
#define D4    (DIM / 4)        // 192 float4 per row

// ---- scratch (static device allocations; no cudaMalloc anywhere) ----
__device__ float g_part[SPLITS * BATCH * DIM];   // 6 MB partial maxes
__device__ float g_xmean[BATCH * DIM];
__device__ float g_invp[POOL];
__device__ float g_xproj[BATCH * DIM];
__device__ float g_xnorm[BATCH * DIM];
__device__ float g_sim[BATCH * POOL];
__device__ int   g_rowidx[BATCH * TOPK];
__device__ int   g_major[TOPK];

__device__ __forceinline__ float4 fmax4(float4 a, float4 b) {
    return make_float4(fmaxf(a.x, b.x), fmaxf(a.y, b.y),
                       fmaxf(a.z, b.z), fmaxf(a.w, b.w));
}

// ---------------- stage 1: token-max (the HBM-bound 403 MB stream) ----------
// grid (SPLITS, BATCH), block 192. Each block max-reduces 64 token rows.
__global__ void k_maxpart(const float* __restrict__ x) {
    int s = blockIdx.x, b = blockIdx.y, tid = threadIdx.x;
    const float4* xp = (const float4*)x + ((size_t)b * TOK + (size_t)s * TOKS) * D4;
    float4 m0 = xp[0 * D4 + tid];
    float4 m1 = xp[1 * D4 + tid];
    float4 m2 = xp[2 * D4 + tid];
    float4 m3 = xp[3 * D4 + tid];
#pragma unroll 4
    for (int t = 4; t < TOKS; t += 4) {
        m0 = fmax4(m0, xp[(t + 0) * D4 + tid]);
        m1 = fmax4(m1, xp[(t + 1) * D4 + tid]);
        m2 = fmax4(m2, xp[(t + 2) * D4 + tid]);
        m3 = fmax4(m3, xp[(t + 3) * D4 + tid]);
    }
    ((float4*)g_part)[(s * BATCH + b) * D4 + tid] = fmax4(fmax4(m0, m1), fmax4(m2, m3));
}

// grid BATCH, block 192: reduce the 32 partials.
__global__ void k_maxfinal() {
    int b = blockIdx.x, tid = threadIdx.x;
    const float4* p4 = (const float4*)g_part;
    float4 m0 = p4[(0 * BATCH + b) * D4 + tid];
    float4 m1 = p4[(1 * BATCH + b) * D4 + tid];
    float4 m2 = p4[(2 * BATCH + b) * D4 + tid];
    float4 m3 = p4[(3 * BATCH + b) * D4 + tid];
#pragma unroll
    for (int s = 4; s < SPLITS; s += 4) {
        m0 = fmax4(m0, p4[((s + 0) * BATCH + b) * D4 + tid]);
        m1 = fmax4(m1, p4[((s + 1) * BATCH + b) * D4 + tid]);
        m2 = fmax4(m2, p4[((s + 2) * BATCH + b) * D4 + tid]);
        m3 = fmax4(m3, p4[((s + 3) * BATCH + b) * D4 + tid]);
    }
    ((float4*)g_xmean)[b * D4 + tid] = fmax4(fmax4(m0, m1), fmax4(m2, m3));
}

// ---------------- stage 2: prompt inverse L2-norms ---------------------------
// grid POOL/8, block 256 (8 warps; one warp per prompt row)
__global__ void k_pnorm(const float* __restrict__ prompt) {
    int w = threadIdx.x >> 5, lane = threadIdx.x & 31;
    int p = blockIdx.x * 8 + w;
    const float* row = prompt + (size_t)p * DIM;
    float s = 0.f;
#pragma unroll
    for (int j = lane; j < DIM; j += 32) { float v = row[j]; s += v * v; }
#pragma unroll
    for (int o = 16; o > 0; o >>= 1) s += __shfl_xor_sync(0xffffffffu, s, o);
    if (lane == 0) g_invp[p] = rsqrtf(fmaxf(s, 1e-12f));
}

// ---------------- stage 3: x_proj = x_mean @ W^T (tiled smem GEMM) ----------
// grid DIM/32, block 256. Tile: all 64 b-rows x 32 output cols.
__global__ void k_proj(const float* __restrict__ W) {
    __shared__ float xs[64][33];
    __shared__ float ws[32][33];
    int tid = threadIdx.x, tx = tid & 31, ty = tid >> 5;
    int o = blockIdx.x * 32 + tx;
    float acc[8];
#pragma unroll
    for (int i = 0; i < 8; i++) acc[i] = 0.f;
    for (int dc = 0; dc < DIM; dc += 32) {
#pragma unroll
        for (int i = 0; i < 8; i++)
            xs[ty + 8 * i][tx] = g_xmean[(ty + 8 * i) * DIM + dc + tx];
#pragma unroll
        for (int i = 0; i < 4; i++)
            ws[ty + 8 * i][tx] = W[(size_t)(blockIdx.x * 32 + ty + 8 * i) * DIM + dc + tx];
        __syncthreads();
#pragma unroll
        for (int kk = 0; kk < 32; kk++) {
            float wv = ws[tx][kk];
#pragma unroll
            for (int i = 0; i < 8; i++) acc[i] += xs[ty + 8 * i][kk] * wv;
        }
        __syncthreads();
    }
#pragma unroll
    for (int i = 0; i < 8; i++) g_xproj[(ty + 8 * i) * DIM + o] = acc[i];
}

// grid BATCH, block 256: row-normalize x_proj -> x_norm
__global__ void k_xnorm() {
    __shared__ float red[256];
    __shared__ float s_inv;
    int b = blockIdx.x, tid = threadIdx.x;
    float s = 0.f;
#pragma unroll
    for (int j = 0; j < 3; j++) {
        float v = g_xproj[b * DIM + tid + 256 * j];
        s += v * v;
    }
    red[tid] = s; __syncthreads();
    for (int st = 128; st > 0; st >>= 1) {
        if (tid < st) red[tid] += red[tid + st];
        __syncthreads();
    }
    if (tid == 0) s_inv = rsqrtf(fmaxf(red[0], 1e-12f));
    __syncthreads();
    float inv = s_inv;
#pragma unroll
    for (int j = 0; j < 3; j++)
        g_xnorm[b * DIM + tid + 256 * j] = g_xproj[b * DIM + tid + 256 * j] * inv;
}

// ---------------- stage 4: similarity = x_norm @ prompt_norm^T --------------
// grid POOL/32, block 256. Tile: all 64 b-rows x 32 prompts.
__global__ void k_sim(const float* __restrict__ prompt) {
    __shared__ float xs[64][33];
    __shared__ float ps[32][33];
    int tid = threadIdx.x, tx = tid & 31, ty = tid >> 5;
    int p = blockIdx.x * 32 + tx;
    float acc[8];
#pragma unroll
    for (int i = 0; i < 8; i++) acc[i] = 0.f;
    for (int dc = 0; dc < DIM; dc += 32) {
#pragma unroll
        for (int i = 0; i < 8; i++)
            xs[ty + 8 * i][tx] = g_xnorm[(ty + 8 * i) * DIM + dc + tx];
#pragma unroll
        for (int i = 0; i < 4; i++)
            ps[ty + 8 * i][tx] = prompt[(size_t)(blockIdx.x * 32 + ty + 8 * i) * DIM + dc + tx];
        __syncthreads();
#pragma unroll
        for (int kk = 0; kk < 32; kk++) {
            float pv = ps[tx][kk];
#pragma unroll
            for (int i = 0; i < 8; i++) acc[i] += xs[ty + 8 * i][kk] * pv;
        }
        __syncthreads();
    }
    float inv = g_invp[p];
#pragma unroll
    for (int i = 0; i < 8; i++) g_sim[(ty + 8 * i) * POOL + p] = acc[i] * inv;
}

// ---------------- stage 5: per-row top-8 (iterative argmax, JAX tie rule) ---
// grid BATCH, block 256
__global__ void k_top8row() {
    __shared__ float sv[POOL];
    __shared__ float rv[256];
    __shared__ int   ri[256];
    int b = blockIdx.x, tid = threadIdx.x;
#pragma unroll
    for (int j = 0; j < 4; j++) sv[tid + 256 * j] = g_sim[b * POOL + tid + 256 * j];
    __syncthreads();
    for (int k = 0; k < TOPK; k++) {
        float bv = -FLT_MAX; int bi = 0;
#pragma unroll
        for (int j = 0; j < 4; j++) {
            int i = tid + 256 * j;
            float v = sv[i];
            if (v > bv) { bv = v; bi = i; }   // ascending i: strict > keeps lowest index on tie
        }
        rv[tid] = bv; ri[tid] = bi; __syncthreads();
        for (int st = 128; st > 0; st >>= 1) {
            if (tid < st) {
                float v2 = rv[tid + st]; int i2 = ri[tid + st];
                if (v2 > rv[tid] || (v2 == rv[tid] && i2 < ri[tid])) { rv[tid] = v2; ri[tid] = i2; }
            }
            __syncthreads();
        }
        if (tid == 0) { g_rowidx[b * TOPK + k] = ri[0]; sv[ri[0]] = -FLT_MAX; }
        __syncthreads();
    }
}

// ---------------- stage 6: vote (bincount + top-8 counts) + reduce_sim ------
// single block, 256 threads
__global__ void k_vote(float* __restrict__ out) {
    __shared__ int   cnt[POOL];
    __shared__ int   rvi[256];
    __shared__ int   ri[256];
    __shared__ float rf[256];
    __shared__ int   major_s[TOPK];
    int tid = threadIdx.x;
    for (int j = tid; j < POOL; j += 256) cnt[j] = 0;
    __syncthreads();
    for (int j = tid; j < BATCH * TOPK; j += 256) atomicAdd(&cnt[g_rowidx[j]], 1);
    __syncthreads();
    for (int k = 0; k < TOPK; k++) {
        int bv = -1, bi = 0;
        for (int j = tid; j < POOL; j += 256) {
            int c = cnt[j];
            if (c > bv) { bv = c; bi = j; }   // ascending j: lowest index wins ties
        }
        rvi[tid] = bv; ri[tid] = bi; __syncthreads();
        for (int st = 128; st > 0; st >>= 1) {
            if (tid < st) {
                int v2 = rvi[tid + st], i2 = ri[tid + st];
                if (v2 > rvi[tid] || (v2 == rvi[tid] && i2 < ri[tid])) { rvi[tid] = v2; ri[tid] = i2; }
            }
            __syncthreads();
        }
        if (tid == 0) { major_s[k] = ri[0]; g_major[k] = ri[0]; cnt[ri[0]] = -1; }
        __syncthreads();
    }
    // reduce_sim = (1/B) * sum_{b,k} sim[b, major[k]]
    float s = 0.f;
    for (int j = tid; j < BATCH * TOPK; j += 256) {
        int b = j >> 3, k = j & 7;
        s += g_sim[b * POOL + major_s[k]];
    }
    rf[tid] = s; __syncthreads();
    for (int st = 128; st > 0; st >>= 1) {
        if (tid < st) rf[tid] += rf[tid + st];
        __syncthreads();
    }
    if (tid == 0) out[0] = rf[0] / (float)BATCH;
}

// ---------------- stage 7: gather batched_prompt ----------------------------
// grid BATCH*TOPK, block 256. out layout: [reduce_sim, batched_prompt(64,8,768)]
__global__ void k_gather(const float* __restrict__ prompt, float* __restrict__ out) {
    int row = blockIdx.x;            // b*8 + k
    int k = row & 7;
    int pid = g_major[k];
    const float* src = prompt + (size_t)pid * DIM;
    float* dst = out + 1 + (size_t)row * DIM;
#pragma unroll
    for (int j = threadIdx.x; j < DIM; j += 256) dst[j] = src[j];
}

extern "C" void kernel_launch(void* const* d_in, const int* in_sizes, int n_in,
                              void* d_out, int out_size) {
    const float* x      = (const float*)d_in[0];   // [64, 2048, 768]
    const float* prompt = (const float*)d_in[1];   // [1024, 768]
    const float* W      = (const float*)d_in[2];   // [768, 768]
    float* out = (float*)d_out;                    // [1 + 64*8*768]

    k_maxpart <<<dim3(SPLITS, BATCH), D4>>>(x);
    k_maxfinal<<<BATCH, D4>>>();
    k_pnorm   <<<POOL / 8, 256>>>(prompt);
    k_proj    <<<DIM / 32, 256>>>(W);
    k_xnorm   <<<BATCH, 256>>>();
    k_sim     <<<POOL / 32, 256>>>(prompt);
    k_top8row <<<BATCH, 256>>>();
    k_vote    <<<1, 256>>>(out);
    k_gather  <<<BATCH * TOPK, 256>>>(prompt, out);
}

// round 2
// speedup vs baseline: 2.0368x; 2.0368x over previous
#include <cuda_runtime.h>
#include <float.h>

#define BATCH 64
#define TOK   2048
#define DIM   768
#define POOL  1024
#define TOPK  8
#define SPLITS 32
#define TOKS  (TOK / SPLITS)   // 64 tokens per split
#define D4    (DIM / 4)        // 192 float4 per row
#define NK    12               // K-splits for GEMMs (768/64)
#define KC    64               // K-chunk per split

// ---- scratch (static device arrays; no cudaMalloc anywhere) ----
__device__ float g_part[SPLITS * BATCH * DIM];     // token-max partials
__device__ float g_xmean[BATCH * DIM];
__device__ float g_invp[POOL];
__device__ float g_xnorm[BATCH * DIM];
__device__ float g_ppart[NK * BATCH * DIM];        // proj split-K partials
__device__ float g_spart[NK * BATCH * POOL];       // sim split-K partials
__device__ float g_sim[BATCH * POOL];
__device__ int   g_rowidx[BATCH * TOPK];
__device__ int   g_major[TOPK];

__device__ __forceinline__ float4 fmax4(float4 a, float4 b) {
    return make_float4(fmaxf(a.x, b.x), fmaxf(a.y, b.y),
                       fmaxf(a.z, b.z), fmaxf(a.w, b.w));
}

// ================= stage 1: token-max (HBM-bound 403 MB stream) =============
// grid (SPLITS, BATCH), block 192
__global__ void k_maxpart(const float* __restrict__ x) {
    int s = blockIdx.x, b = blockIdx.y, tid = threadIdx.x;
    const float4* xp = (const float4*)x + ((size_t)b * TOK + (size_t)s * TOKS) * D4;
    float4 m0 = xp[0 * D4 + tid];
    float4 m1 = xp[1 * D4 + tid];
    float4 m2 = xp[2 * D4 + tid];
    float4 m3 = xp[3 * D4 + tid];
#pragma unroll 4
    for (int t = 4; t < TOKS; t += 4) {
        m0 = fmax4(m0, xp[(t + 0) * D4 + tid]);
        m1 = fmax4(m1, xp[(t + 1) * D4 + tid]);
        m2 = fmax4(m2, xp[(t + 2) * D4 + tid]);
        m3 = fmax4(m3, xp[(t + 3) * D4 + tid]);
    }
    ((float4*)g_part)[(s * BATCH + b) * D4 + tid] = fmax4(fmax4(m0, m1), fmax4(m2, m3));
}

// grid BATCH, block 192
__global__ void k_maxfinal() {
    int b = blockIdx.x, tid = threadIdx.x;
    const float4* p4 = (const float4*)g_part;
    float4 m0 = p4[(0 * BATCH + b) * D4 + tid];
    float4 m1 = p4[(1 * BATCH + b) * D4 + tid];
    float4 m2 = p4[(2 * BATCH + b) * D4 + tid];
    float4 m3 = p4[(3 * BATCH + b) * D4 + tid];
#pragma unroll
    for (int s = 4; s < SPLITS; s += 4) {
        m0 = fmax4(m0, p4[((s + 0) * BATCH + b) * D4 + tid]);
        m1 = fmax4(m1, p4[((s + 1) * BATCH + b) * D4 + tid]);
        m2 = fmax4(m2, p4[((s + 2) * BATCH + b) * D4 + tid]);
        m3 = fmax4(m3, p4[((s + 3) * BATCH + b) * D4 + tid]);
    }
    ((float4*)g_xmean)[b * D4 + tid] = fmax4(fmax4(m0, m1), fmax4(m2, m3));
}

// ================= stage 2: prompt inverse L2-norms ==========================
// grid POOL/8, block 256 (one warp per prompt row)
__global__ void k_pnorm(const float* __restrict__ prompt) {
    int w = threadIdx.x >> 5, lane = threadIdx.x & 31;
    int p = blockIdx.x * 8 + w;
    const float* row = prompt + (size_t)p * DIM;
    float s = 0.f;
#pragma unroll
    for (int j = lane; j < DIM; j += 32) { float v = row[j]; s += v * v; }
#pragma unroll
    for (int o = 16; o > 0; o >>= 1) s += __shfl_xor_sync(0xffffffffu, s, o);
    if (lane == 0) g_invp[p] = rsqrtf(fmaxf(s, 1e-12f));
}

// ================= split-K GEMM: C_part[split] = A(64xKC) @ B_tile^T =========
// block 256, computes 64 rows x 64 cols for one K-chunk.
// A: [64, DIM] row-major. B: [nrowsB, DIM] row-major (dot along DIM).
// part layout: [split][64][CSTRIDE]
__device__ __forceinline__ void gemm_part_body(
    const float* __restrict__ A, const float* __restrict__ B,
    float* __restrict__ part, int cstride)
{
    __shared__ float xs[64][68];
    __shared__ float ws[64][68];
    int tid = threadIdx.x;
    int kc0 = blockIdx.y * KC;
    int c0  = blockIdx.x * 64;
#pragma unroll
    for (int it = 0; it < 4; it++) {
        int idx = tid + it * 256;          // 0..1023
        int r = idx >> 4, c4 = idx & 15;
        *(float4*)&xs[r][c4 * 4] = *(const float4*)(A + (size_t)r * DIM + kc0 + c4 * 4);
        *(float4*)&ws[r][c4 * 4] = *(const float4*)(B + (size_t)(c0 + r) * DIM + kc0 + c4 * 4);
    }
    __syncthreads();
    int tx = tid & 15, ty = tid >> 4;      // 16 x 16 thread grid, 4x4 micro-tile
    float acc[4][4];
#pragma unroll
    for (int i = 0; i < 4; i++)
#pragma unroll
        for (int j = 0; j < 4; j++) acc[i][j] = 0.f;
#pragma unroll
    for (int k4 = 0; k4 < KC / 4; k4++) {
        float4 a[4], b[4];
#pragma unroll
        for (int i = 0; i < 4; i++) a[i] = *(float4*)&xs[ty * 4 + i][k4 * 4];
#pragma unroll
        for (int j = 0; j < 4; j++) b[j] = *(float4*)&ws[tx * 4 + j][k4 * 4];
#pragma unroll
        for (int i = 0; i < 4; i++)
#pragma unroll
            for (int j = 0; j < 4; j++) {
                acc[i][j] += a[i].x * b[j].x;
                acc[i][j] += a[i].y * b[j].y;
                acc[i][j] += a[i].z * b[j].z;
                acc[i][j] += a[i].w * b[j].w;
            }
    }
    float* dst = part + (size_t)blockIdx.y * BATCH * cstride;
#pragma unroll
    for (int i = 0; i < 4; i++) {
        float4 v = make_float4(acc[i][0], acc[i][1], acc[i][2], acc[i][3]);
        *(float4*)(dst + (size_t)(ty * 4 + i) * cstride + c0 + tx * 4) = v;
    }
}

// grid (DIM/64, NK): x_proj partials = x_mean @ W^T
__global__ void k_proj_part(const float* __restrict__ W) {
    gemm_part_body(g_xmean, W, g_ppart, DIM);
}
// grid (POOL/64, NK): sim partials = x_norm @ prompt^T (unnormalized)
__global__ void k_sim_part(const float* __restrict__ prompt) {
    gemm_part_body(g_xnorm, prompt, g_spart, POOL);
}

// ================= reduce proj partials + row L2-normalize ===================
// grid BATCH, block 256
__global__ void k_xnorm_red() {
    __shared__ float red[256];
    __shared__ float s_inv;
    int b = blockIdx.x, tid = threadIdx.x;
    float v[3];
    float ss = 0.f;
#pragma unroll
    for (int j = 0; j < 3; j++) {
        int col = tid + 256 * j;
        float s = 0.f;
#pragma unroll
        for (int sp = 0; sp < NK; sp++)
            s += g_ppart[(size_t)sp * BATCH * DIM + (size_t)b * DIM + col];
        v[j] = s;
        ss += s * s;
    }
    red[tid] = ss; __syncthreads();
    for (int st = 128; st > 0; st >>= 1) {
        if (tid < st) red[tid] += red[tid + st];
        __syncthreads();
    }
    if (tid == 0) s_inv = rsqrtf(fmaxf(red[0], 1e-12f));
    __syncthreads();
    float inv = s_inv;
#pragma unroll
    for (int j = 0; j < 3; j++)
        g_xnorm[b * DIM + tid + 256 * j] = v[j] * inv;
}

// ================= reduce sim partials, scale by prompt inv-norm =============
// grid BATCH*POOL/256, block 256
__global__ void k_simred() {
    int idx = blockIdx.x * 256 + threadIdx.x;   // b*POOL + p
    int p = idx & (POOL - 1);
    float s = 0.f;
#pragma unroll
    for (int sp = 0; sp < NK; sp++)
        s += g_spart[(size_t)sp * BATCH * POOL + idx];
    g_sim[idx] = s * g_invp[p];
}

// ================= per-row top-8: one warp per batch row, registers only ====
// grid BATCH, block 32
__global__ void k_top8row() {
    int b = blockIdx.x, lane = threadIdx.x;
    float v[32];
#pragma unroll
    for (int j = 0; j < 32; j++) v[j] = g_sim[b * POOL + lane + 32 * j];
    for (int k = 0; k < TOPK; k++) {
        float bv = -FLT_MAX; int bj = 0;
#pragma unroll
        for (int j = 0; j < 32; j++)
            if (v[j] > bv) { bv = v[j]; bj = j; }     // ascending j: lowest local idx on tie
        float rv = bv; int rgi = lane + 32 * bj;
#pragma unroll
        for (int o = 16; o > 0; o >>= 1) {
            float ov = __shfl_xor_sync(0xffffffffu, rv, o);
            int   oi = __shfl_xor_sync(0xffffffffu, rgi, o);
            if (ov > rv || (ov == rv && oi < rgi)) { rv = ov; rgi = oi; }
        }
        if (lane == 0) g_rowidx[b * TOPK + k] = rgi;
        if (lane == (rgi & 31)) {
            int slot = rgi >> 5;
#pragma unroll
            for (int j = 0; j < 32; j++)
                if (j == slot) v[j] = -FLT_MAX;
        }
    }
}

// ================= vote (bincount + top-8 over counts) + reduce_sim ==========
// single block, 256 threads
__global__ void k_vote(float* __restrict__ out) {
    __shared__ int   cnt[POOL];
    __shared__ int   rvi[256];
    __shared__ int   ri[256];
    __shared__ float rf[256];
    __shared__ int   major_s[TOPK];
    int tid = threadIdx.x;
    for (int j = tid; j < POOL; j += 256) cnt[j] = 0;
    __syncthreads();
    for (int j = tid; j < BATCH * TOPK; j += 256) atomicAdd(&cnt[g_rowidx[j]], 1);
    __syncthreads();
    for (int k = 0; k < TOPK; k++) {
        int bv = -1, bi = 0;
        for (int j = tid; j < POOL; j += 256) {
            int c = cnt[j];
            if (c > bv) { bv = c; bi = j; }   // ascending j: lowest index on tie
        }
        rvi[tid] = bv; ri[tid] = bi; __syncthreads();
        for (int st = 128; st > 0; st >>= 1) {
            if (tid < st) {
                int v2 = rvi[tid + st], i2 = ri[tid + st];
                if (v2 > rvi[tid] || (v2 == rvi[tid] && i2 < ri[tid])) { rvi[tid] = v2; ri[tid] = i2; }
            }
            __syncthreads();
        }
        if (tid == 0) { major_s[k] = ri[0]; g_major[k] = ri[0]; cnt[ri[0]] = -1; }
        __syncthreads();
    }
    float s = 0.f;
    for (int j = tid; j < BATCH * TOPK; j += 256) {
        int b = j >> 3, k = j & 7;
        s += g_sim[b * POOL + major_s[k]];
    }
    rf[tid] = s; __syncthreads();
    for (int st = 128; st > 0; st >>= 1) {
        if (tid < st) rf[tid] += rf[tid + st];
        __syncthreads();
    }
    if (tid == 0) out[0] = rf[0] / (float)BATCH;
}

// ================= gather batched_prompt =====================================
// grid BATCH*TOPK, block 192 (float4 copies)
__global__ void k_gather(const float* __restrict__ prompt, float* __restrict__ out) {
    int row = blockIdx.x;            // b*8 + k
    int k = row & 7;
    int pid = g_major[k];
    const float* src = prompt + (size_t)pid * DIM;
    float* dst = out + 1 + (size_t)row * DIM;
    dst[threadIdx.x]       = src[threadIdx.x];
    dst[threadIdx.x + 192] = src[threadIdx.x + 192];
    dst[threadIdx.x + 384] = src[threadIdx.x + 384];
    dst[threadIdx.x + 576] = src[threadIdx.x + 576];
}

extern "C" void kernel_launch(void* const* d_in, const int* in_sizes, int n_in,
                              void* d_out, int out_size) {
    const float* x      = (const float*)d_in[0];   // [64, 2048, 768]
    const float* prompt = (const float*)d_in[1];   // [1024, 768]
    const float* W      = (const float*)d_in[2];   // [768, 768]
    float* out = (float*)d_out;                    // [1 + 64*8*768]

    k_maxpart  <<<dim3(SPLITS, BATCH), D4>>>(x);
    k_maxfinal <<<BATCH, D4>>>();
    k_pnorm    <<<POOL / 8, 256>>>(prompt);
    k_proj_part<<<dim3(DIM / 64, NK), 256>>>(W);
    k_xnorm_red<<<BATCH, 256>>>();
    k_sim_part <<<dim3(POOL / 64, NK), 256>>>(prompt);
    k_simred   <<<BATCH * POOL / 256, 256>>>();
    k_top8row  <<<BATCH, 32>>>();
    k_vote     <<<1, 256>>>(out);
    k_gather   <<<BATCH * TOPK, 192>>>(prompt, out);
}